// round 3
// baseline (speedup 1.0000x reference)
#include <cuda_runtime.h>
#include <cuda_bf16.h>
#include <cstdint>

// ============================================================================
// Problem constants
// ============================================================================
#define B_DIM   256
#define T_DIM   2048
#define K_DIM   64
#define H_DIM   128
#define TILE_T  32
#define N_TILES (T_DIM / TILE_T)   // 64

// sigmoid(5*(mem-1)) = 1 / (1 + 2^(C1*mem + C0))
#define SIG_C1  (-7.2134752044448169f)   // -5 * log2(e)
#define SIG_C0  ( 7.2134752044448169f)
#define SIG_DC1 (-6.4921276840003352f)   // 0.9 * C1

// ============================================================================
// SMEM layout (bytes). Rows padded to 72 halves (144 B) for conflict-free LDSM.
// ============================================================================
#define WSTR      72
#define ROWB      144
#define SMEM_W_HI 0                        // 128 x 72 halves = 18432 B
#define SMEM_W_LO 18432
#define SMEM_X    36864                    // 2 buffers x (hi 4608 + lo 4608)
#define XBUF(s)   (SMEM_X + (s) * 9216)
#define FF_STR    33                       // floats per ff row (pad)
#define SMEM_FF   55296                    // 4 warps x 32*33*4 = 4224 B
#define SMEM_TOTAL 72192

// ============================================================================
// Helpers
// ============================================================================
__device__ __forceinline__ uint32_t smem_to_u32(const void* p) {
    uint32_t a;
    asm("{ .reg .u64 t; cvta.to.shared.u64 t, %1; cvt.u32.u64 %0, t; }"
        : "=r"(a) : "l"(p));
    return a;
}
__device__ __forceinline__ float ex2f(float x) {
    float y; asm("ex2.approx.f32 %0, %1;" : "=f"(y) : "f"(x)); return y;
}
__device__ __forceinline__ float rcpf(float x) {
    float y; asm("rcp.approx.f32 %0, %1;" : "=f"(y) : "f"(x)); return y;
}
__device__ __forceinline__ void ldm_x4(uint32_t* r, uint32_t addr) {
    asm volatile("ldmatrix.sync.aligned.m8n8.x4.shared.b16 {%0,%1,%2,%3}, [%4];"
        : "=r"(r[0]), "=r"(r[1]), "=r"(r[2]), "=r"(r[3]) : "r"(addr));
}
__device__ __forceinline__ void mma_bf16(float* d, const uint32_t* a, const uint32_t* b) {
    asm volatile(
        "mma.sync.aligned.m16n8k16.row.col.f32.bf16.bf16.f32 "
        "{%0,%1,%2,%3},{%4,%5,%6,%7},{%8,%9},{%0,%1,%2,%3};"
        : "+f"(d[0]), "+f"(d[1]), "+f"(d[2]), "+f"(d[3])
        : "r"(a[0]), "r"(a[1]), "r"(a[2]), "r"(a[3]), "r"(b[0]), "r"(b[1]));
}
__device__ __forceinline__ uint32_t pack_bf16(__nv_bfloat16 a, __nv_bfloat16 b) {
    return ((uint32_t)__bfloat16_as_ushort(b) << 16) | __bfloat16_as_ushort(a);
}
__device__ __forceinline__ void cvt_pack(float4 v, uint2& hi, uint2& lo) {
    __nv_bfloat16 h0 = __float2bfloat16(v.x);
    __nv_bfloat16 h1 = __float2bfloat16(v.y);
    __nv_bfloat16 h2 = __float2bfloat16(v.z);
    __nv_bfloat16 h3 = __float2bfloat16(v.w);
    __nv_bfloat16 l0 = __float2bfloat16(v.x - __bfloat162float(h0));
    __nv_bfloat16 l1 = __float2bfloat16(v.y - __bfloat162float(h1));
    __nv_bfloat16 l2 = __float2bfloat16(v.z - __bfloat162float(h2));
    __nv_bfloat16 l3 = __float2bfloat16(v.w - __bfloat162float(h3));
    hi.x = pack_bf16(h0, h1); hi.y = pack_bf16(h2, h3);
    lo.x = pack_bf16(l0, l1); lo.y = pack_bf16(l2, l3);
}

// ============================================================================
// Merged-role kernel: 1 CTA / batch, 128 threads = 4 warps.
// Warp wp owns heads [32wp, 32wp+32): does its own GEMM slice (A = W frags
// in registers) AND the neuron scan, software-pipelined per 32-timestep tile.
// ============================================================================
__global__ void __launch_bounds__(128, 2)
snn_encoder_kernel(const float* __restrict__ x, const float* __restrict__ W,
                   const float* __restrict__ bvec, float* __restrict__ out) {
    extern __shared__ char smem[];
    const uint32_t sb = smem_to_u32(smem);
    const int tid  = threadIdx.x;
    const int lane = tid & 31;
    const int wp   = tid >> 5;
    const int b    = blockIdx.x;
    const float* xb = x + (size_t)b * T_DIM * K_DIM;

    // ---- Cooperative W convert: 128x64 fp32 -> padded bf16 hi/lo tiles
    {
        const float4* w4 = reinterpret_cast<const float4*>(W);
#pragma unroll
        for (int q = 0; q < 16; ++q) {
            int idx = tid + (q << 7);            // 2048 float4
            float4 v = __ldg(&w4[idx]);
            int row = idx >> 4, c4 = idx & 15;
            uint32_t off = (uint32_t)row * ROWB + c4 * 8;
            uint2 hi, lo; cvt_pack(v, hi, lo);
            *reinterpret_cast<uint2*>(smem + SMEM_W_HI + off) = hi;
            *reinterpret_cast<uint2*>(smem + SMEM_W_LO + off) = lo;
        }
    }
    __syncthreads();

    // ---- ldmatrix lane offsets (validated in R2)
    const int j = lane >> 3;
    const uint32_t a_off = (uint32_t)(((j & 1) * 8 + (lane & 7)) * WSTR + ((j >> 1) * 8)) * 2;
    const uint32_t b_off = (uint32_t)(((j >> 1) * 8 + (lane & 7)) * WSTR + ((j & 1) * 8)) * 2;

    // ---- Hoist W A-fragments (hi & lo) into registers: [mt][ks][4]
    uint32_t Ahi[2][4][4], Alo[2][4][4];
    {
        const uint32_t aW_hi = sb + SMEM_W_HI + (uint32_t)(wp * 32) * ROWB + a_off;
        const uint32_t aW_lo = sb + SMEM_W_LO + (uint32_t)(wp * 32) * ROWB + a_off;
#pragma unroll
        for (int mt = 0; mt < 2; ++mt)
#pragma unroll
            for (int ks = 0; ks < 4; ++ks) {
                ldm_x4(Ahi[mt][ks], aW_hi + (uint32_t)mt * 16 * ROWB + ks * 32);
                ldm_x4(Alo[mt][ks], aW_lo + (uint32_t)mt * 16 * ROWB + ks * 32);
            }
    }

    // ---- Bias per accumulator row (folded into D init — free bias add)
    const int r0 = lane >> 2;
    const int c0 = 2 * (lane & 3);
    float bias0[2], bias1[2];
#pragma unroll
    for (int mt = 0; mt < 2; ++mt) {
        bias0[mt] = __ldg(&bvec[wp * 32 + mt * 16 + r0]);
        bias1[mt] = __ldg(&bvec[wp * 32 + mt * 16 + r0 + 8]);
    }

    float* const ffp = reinterpret_cast<float*>(smem + SMEM_FF + wp * 4224);
    float* const outp = out + (size_t)b * T_DIM * H_DIM + wp * 32 + lane;

    float4 xr[4];
    float d[2][4][4];
    float r[TILE_T];

    // ================= Prologue =================
    // Load + convert x tile 0
    {
        const float4* xt4 = reinterpret_cast<const float4*>(xb);
#pragma unroll
        for (int q = 0; q < 4; ++q) xr[q] = __ldg(&xt4[tid + (q << 7)]);
#pragma unroll
        for (int q = 0; q < 4; ++q) {
            int idx = tid + (q << 7);
            int row = idx >> 4, c4 = idx & 15;
            uint32_t off = (uint32_t)row * ROWB + c4 * 8;
            uint2 hi, lo; cvt_pack(xr[q], hi, lo);
            *reinterpret_cast<uint2*>(smem + XBUF(0) + off)        = hi;
            *reinterpret_cast<uint2*>(smem + XBUF(0) + 4608 + off) = lo;
        }
    }
    // prefetch x tile 1
    {
        const float4* xt4 = reinterpret_cast<const float4*>(xb + (size_t)TILE_T * K_DIM);
#pragma unroll
        for (int q = 0; q < 4; ++q) xr[q] = __ldg(&xt4[tid + (q << 7)]);
    }
    __syncthreads();

    // GEMM tile 0 -> r[]
    {
#pragma unroll
        for (int mt = 0; mt < 2; ++mt)
#pragma unroll
            for (int nt = 0; nt < 4; ++nt) {
                d[mt][nt][0] = bias0[mt]; d[mt][nt][1] = bias0[mt];
                d[mt][nt][2] = bias1[mt]; d[mt][nt][3] = bias1[mt];
            }
        const uint32_t bX_hi = sb + XBUF(0) + b_off;
        const uint32_t bX_lo = bX_hi + 4608;
#pragma unroll
        for (int ks = 0; ks < 4; ++ks) {
            uint32_t bh[2][4], bl[2][4];
            ldm_x4(bh[0], bX_hi + ks * 32);
            ldm_x4(bh[1], bX_hi + 16 * ROWB + ks * 32);
            ldm_x4(bl[0], bX_lo + ks * 32);
            ldm_x4(bl[1], bX_lo + 16 * ROWB + ks * 32);
#pragma unroll
            for (int mt = 0; mt < 2; ++mt)
#pragma unroll
                for (int nt = 0; nt < 4; ++nt) {
                    const uint32_t* bhp = &bh[nt >> 1][(nt & 1) * 2];
                    const uint32_t* blp = &bl[nt >> 1][(nt & 1) * 2];
                    mma_bf16(d[mt][nt], Ahi[mt][ks], bhp);
                    mma_bf16(d[mt][nt], Ahi[mt][ks], blp);
                    mma_bf16(d[mt][nt], Alo[mt][ks], bhp);
                }
        }
        // transpose fragment -> per-warp ff rows
#pragma unroll
        for (int mt = 0; mt < 2; ++mt) {
            int row = mt * 16 + r0;
#pragma unroll
            for (int nt = 0; nt < 4; ++nt) {
                int col = nt * 8 + c0;
                ffp[row * FF_STR + col]           = d[mt][nt][0];
                ffp[row * FF_STR + col + 1]       = d[mt][nt][1];
                ffp[(row + 8) * FF_STR + col]     = d[mt][nt][2];
                ffp[(row + 8) * FF_STR + col + 1] = d[mt][nt][3];
            }
        }
        __syncwarp();
#pragma unroll
        for (int t = 0; t < TILE_T; ++t) r[t] = ffp[lane * FF_STR + t];
    }
    // convert prefetched x tile 1
    {
#pragma unroll
        for (int q = 0; q < 4; ++q) {
            int idx = tid + (q << 7);
            int row = idx >> 4, c4 = idx & 15;
            uint32_t off = (uint32_t)row * ROWB + c4 * 8;
            uint2 hi, lo; cvt_pack(xr[q], hi, lo);
            *reinterpret_cast<uint2*>(smem + XBUF(1) + off)        = hi;
            *reinterpret_cast<uint2*>(smem + XBUF(1) + 4608 + off) = lo;
        }
    }
    __syncthreads();

    // ================= Main loop =================
    float mem = 0.0f, spk = 0.0f, wv = SIG_C0;

    for (int i = 0; i < N_TILES; ++i) {
        const int s = i & 1;
        const bool have1 = (i + 1 < N_TILES);   // GEMM tile i+1 this iter
        const bool have2 = (i + 2 < N_TILES);   // prefetch tile i+2

        if (have2) {
            const float4* xt4 = reinterpret_cast<const float4*>(
                xb + (size_t)(i + 2) * TILE_T * K_DIM);
#pragma unroll
            for (int q = 0; q < 4; ++q) xr[q] = __ldg(&xt4[tid + (q << 7)]);
        }

        if (have1) {
#pragma unroll
            for (int mt = 0; mt < 2; ++mt)
#pragma unroll
                for (int nt = 0; nt < 4; ++nt) {
                    d[mt][nt][0] = bias0[mt]; d[mt][nt][1] = bias0[mt];
                    d[mt][nt][2] = bias1[mt]; d[mt][nt][3] = bias1[mt];
                }
        }
        const uint32_t bX_hi = sb + XBUF(s ^ 1) + b_off;
        const uint32_t bX_lo = bX_hi + 4608;
        float* po = outp + (size_t)i * TILE_T * H_DIM;

        // ---- interleave: 8 scan steps (latency chain) + 1 GEMM ks-chunk
#pragma unroll
        for (int ck = 0; ck < 4; ++ck) {
#pragma unroll
            for (int tt = 0; tt < 8; ++tt) {
                const int t = ck * 8 + tt;
                float p = r[t] - spk;                // ff (incl bias) - spk
                float z = fmaf(p, SIG_C1, wv);       // C1*mem_new + C0
                mem = fmaf(0.9f, mem, p);
                wv  = fmaf(mem, SIG_DC1, SIG_C0);    // for next step
                float e = ex2f(z);
                spk = rcpf(1.0f + e);                // sigmoid(5*(mem-1))
                po[(size_t)t * H_DIM] = spk;
            }
            if (have1) {
                const int ks = ck;
                uint32_t bh[2][4], bl[2][4];
                ldm_x4(bh[0], bX_hi + ks * 32);
                ldm_x4(bh[1], bX_hi + 16 * ROWB + ks * 32);
                ldm_x4(bl[0], bX_lo + ks * 32);
                ldm_x4(bl[1], bX_lo + 16 * ROWB + ks * 32);
#pragma unroll
                for (int mt = 0; mt < 2; ++mt)
#pragma unroll
                    for (int nt = 0; nt < 4; ++nt) {
                        const uint32_t* bhp = &bh[nt >> 1][(nt & 1) * 2];
                        const uint32_t* blp = &bl[nt >> 1][(nt & 1) * 2];
                        mma_bf16(d[mt][nt], Ahi[mt][ks], bhp);
                        mma_bf16(d[mt][nt], Ahi[mt][ks], blp);
                        mma_bf16(d[mt][nt], Alo[mt][ks], bhp);
                    }
            }
        }

        // ---- ff fragment -> rows -> registers for next tile's scan
        if (have1) {
#pragma unroll
            for (int mt = 0; mt < 2; ++mt) {
                int row = mt * 16 + r0;
#pragma unroll
                for (int nt = 0; nt < 4; ++nt) {
                    int col = nt * 8 + c0;
                    ffp[row * FF_STR + col]           = d[mt][nt][0];
                    ffp[row * FF_STR + col + 1]       = d[mt][nt][1];
                    ffp[(row + 8) * FF_STR + col]     = d[mt][nt][2];
                    ffp[(row + 8) * FF_STR + col + 1] = d[mt][nt][3];
                }
            }
            __syncwarp();
#pragma unroll
            for (int t = 0; t < TILE_T; ++t) r[t] = ffp[lane * FF_STR + t];
        }

        // ---- convert prefetched tile i+2 into buffer s
        if (have2) {
#pragma unroll
            for (int q = 0; q < 4; ++q) {
                int idx = tid + (q << 7);
                int row = idx >> 4, c4 = idx & 15;
                uint32_t off = (uint32_t)row * ROWB + c4 * 8;
                uint2 hi, lo; cvt_pack(xr[q], hi, lo);
                *reinterpret_cast<uint2*>(smem + XBUF(s) + off)        = hi;
                *reinterpret_cast<uint2*>(smem + XBUF(s) + 4608 + off) = lo;
            }
        }
        __syncthreads();
    }
}

// ============================================================================
// Launch. Inputs: x [256,2048,64] f32, W [128,64] f32, b [128] f32 -> out f32
// ============================================================================
extern "C" void kernel_launch(void* const* d_in, const int* in_sizes, int n_in,
                              void* d_out, int out_size) {
    const float* x = (const float*)d_in[0];
    const float* W = (const float*)d_in[1];
    const float* b = (const float*)d_in[2];
    float* out = (float*)d_out;

    cudaFuncSetAttribute(snn_encoder_kernel,
                         cudaFuncAttributeMaxDynamicSharedMemorySize, SMEM_TOTAL);
    snn_encoder_kernel<<<B_DIM, 128, SMEM_TOTAL>>>(x, W, b, out);
}

// round 4
// speedup vs baseline: 1.4924x; 1.4924x over previous
#include <cuda_runtime.h>
#include <cuda_bf16.h>
#include <cstdint>

// ============================================================================
// Problem constants
// ============================================================================
#define B_DIM   256
#define T_DIM   2048
#define K_DIM   64
#define H_DIM   128
#define TILE_T  32
#define N_TILES (T_DIM / TILE_T)   // 64

// spk = sigmoid(5(mem-1)) = 0.5*tanh(2.5*mem - 2.5) + 0.5
// chain: p = ff - spk; y = 2.5p + wv; th = tanh(y); spk = 0.5th + 0.5
// off-chain: mem' = 0.9mem + p; wv = 2.25*mem' - 2.5

// ============================================================================
// SMEM layout (bytes)
//   [0, 18432)        x double buffer (2 x 32 rows x 144 B, hi+lo halves)
//   [18432, 36864)    W_lo persistent (128 x 144 B)
//   [36864, 87552)    ff ring, 3 slots x 16896 B ([t][h] stride 132 floats)
//   W_hi (init only) aliases the ff region at 36864.
// ============================================================================
#define WSTR      72
#define ROWB      144
#define XBUF(s)   ((s) * 9216)            // hi at +0 (4608), lo at +4608
#define SMEM_W_LO 18432
#define SMEM_FF   36864
#define FFB(s)    (SMEM_FF + (s) * 16896)
#define FF_STR    132                      // floats per t-row (conflict-free)
#define SMEM_W_HI 36864                    // init-time alias
#define SMEM_TOTAL 87552

// ============================================================================
// Helpers
// ============================================================================
__device__ __forceinline__ uint32_t smem_to_u32(const void* p) {
    uint32_t a;
    asm("{ .reg .u64 t; cvta.to.shared.u64 t, %1; cvt.u32.u64 %0, t; }"
        : "=r"(a) : "l"(p));
    return a;
}
__device__ __forceinline__ float tanhf_approx(float x) {
    float y; asm("tanh.approx.f32 %0, %1;" : "=f"(y) : "f"(x)); return y;
}
__device__ __forceinline__ void ldm_x4(uint32_t* r, uint32_t addr) {
    asm volatile("ldmatrix.sync.aligned.m8n8.x4.shared.b16 {%0,%1,%2,%3}, [%4];"
        : "=r"(r[0]), "=r"(r[1]), "=r"(r[2]), "=r"(r[3]) : "r"(addr));
}
__device__ __forceinline__ void mma_bf16(float* d, const uint32_t* a, const uint32_t* b) {
    asm volatile(
        "mma.sync.aligned.m16n8k16.row.col.f32.bf16.bf16.f32 "
        "{%0,%1,%2,%3},{%4,%5,%6,%7},{%8,%9},{%0,%1,%2,%3};"
        : "+f"(d[0]), "+f"(d[1]), "+f"(d[2]), "+f"(d[3])
        : "r"(a[0]), "r"(a[1]), "r"(a[2]), "r"(a[3]), "r"(b[0]), "r"(b[1]));
}
__device__ __forceinline__ uint32_t pack_bf16(__nv_bfloat16 a, __nv_bfloat16 b) {
    return ((uint32_t)__bfloat16_as_ushort(b) << 16) | __bfloat16_as_ushort(a);
}
__device__ __forceinline__ void cvt_pack(float4 v, uint2& hi, uint2& lo) {
    __nv_bfloat16 h0 = __float2bfloat16(v.x);
    __nv_bfloat16 h1 = __float2bfloat16(v.y);
    __nv_bfloat16 h2 = __float2bfloat16(v.z);
    __nv_bfloat16 h3 = __float2bfloat16(v.w);
    __nv_bfloat16 l0 = __float2bfloat16(v.x - __bfloat162float(h0));
    __nv_bfloat16 l1 = __float2bfloat16(v.y - __bfloat162float(h1));
    __nv_bfloat16 l2 = __float2bfloat16(v.z - __bfloat162float(h2));
    __nv_bfloat16 l3 = __float2bfloat16(v.w - __bfloat162float(h3));
    hi.x = pack_bf16(h0, h1); hi.y = pack_bf16(h2, h3);
    lo.x = pack_bf16(l0, l1); lo.y = pack_bf16(l2, l3);
}

#define BAR_SYNC(id)   asm volatile("bar.sync %0, 256;"   :: "r"(id) : "memory")
#define BAR_ARRIVE(id) asm volatile("bar.arrive %0, 256;" :: "r"(id) : "memory")
// READY(s) = 1+s, FREE(s) = 4+s, producer-internal = 7

// ============================================================================
// Warp-specialized kernel. 1 CTA / batch, 256 threads.
//   tid 0..127  : consumers — thread = head, pure tanh scan chain
//   tid 128..255: producers — bf16-split HMMA GEMM into 3-slot ff ring
// ============================================================================
__global__ void __launch_bounds__(256, 2)
snn_encoder_kernel(const float* __restrict__ x, const float* __restrict__ W,
                   const float* __restrict__ bvec, float* __restrict__ out) {
    extern __shared__ char smem[];
    const uint32_t sb = smem_to_u32(smem);
    const int tid = threadIdx.x;
    const int b   = blockIdx.x;
    const float* xb = x + (size_t)b * T_DIM * K_DIM;

    // ---- Cooperative W convert: 128x64 fp32 -> bf16 hi/lo (hi aliases ff)
    {
        const float4* w4 = reinterpret_cast<const float4*>(W);
#pragma unroll
        for (int q = 0; q < 8; ++q) {
            int idx = tid + (q << 8);            // 2048 float4
            float4 v = __ldg(&w4[idx]);
            int row = idx >> 4, c4 = idx & 15;
            uint32_t off = (uint32_t)row * ROWB + c4 * 8;
            uint2 hi, lo; cvt_pack(v, hi, lo);
            *reinterpret_cast<uint2*>(smem + SMEM_W_HI + off) = hi;
            *reinterpret_cast<uint2*>(smem + SMEM_W_LO + off) = lo;
        }
    }
    __syncthreads();

    if (tid >= 128) {
        // ==================== PRODUCERS ====================
        const int pt   = tid - 128;
        const int lane = pt & 31;
        const int pw   = pt >> 5;                // heads [32pw, 32pw+32)
        const int j    = lane >> 3;

        const uint32_t a_off = (uint32_t)(((j & 1) * 8 + (lane & 7)) * WSTR + ((j >> 1) * 8)) * 2;
        const uint32_t b_off = (uint32_t)(((j >> 1) * 8 + (lane & 7)) * WSTR + ((j & 1) * 8)) * 2;
        const uint32_t aW_lo = sb + SMEM_W_LO + (uint32_t)(pw * 32) * ROWB + a_off;

        // hoist W_hi fragments into registers (before ff ring overwrites them)
        uint32_t Ahi[2][4][4];
        {
            const uint32_t aW_hi = sb + SMEM_W_HI + (uint32_t)(pw * 32) * ROWB + a_off;
#pragma unroll
            for (int mt = 0; mt < 2; ++mt)
#pragma unroll
                for (int ks = 0; ks < 4; ++ks)
                    ldm_x4(Ahi[mt][ks], aW_hi + (uint32_t)mt * 16 * ROWB + ks * 32);
        }

        // bias per accumulator row (folded into D init)
        const int r0 = lane >> 2;
        const int c0 = 2 * (lane & 3);
        float bias0[2], bias1[2];
#pragma unroll
        for (int mt = 0; mt < 2; ++mt) {
            bias0[mt] = __ldg(&bvec[pw * 32 + mt * 16 + r0]);
            bias1[mt] = __ldg(&bvec[pw * 32 + mt * 16 + r0 + 8]);
        }

        // prologue: load + convert x tile 0 into XBUF(0)
        float4 xr[4];
        {
            const float4* xt4 = reinterpret_cast<const float4*>(xb);
#pragma unroll
            for (int q = 0; q < 4; ++q) xr[q] = __ldg(&xt4[pt + (q << 7)]);
#pragma unroll
            for (int q = 0; q < 4; ++q) {
                int idx = pt + (q << 7);
                int row = idx >> 4, c4 = idx & 15;
                uint32_t off = (uint32_t)row * ROWB + c4 * 8;
                uint2 hi, lo; cvt_pack(xr[q], hi, lo);
                *reinterpret_cast<uint2*>(smem + XBUF(0) + off)        = hi;
                *reinterpret_cast<uint2*>(smem + XBUF(0) + 4608 + off) = lo;
            }
        }
        asm volatile("bar.sync 7, 128;" ::: "memory");

        for (int i = 0; i < N_TILES; ++i) {
            const int s = i - (i / 3) * 3;       // i % 3
            const bool havenext = (i + 1 < N_TILES);

            // prefetch next x tile (DRAM latency hidden behind GEMM)
            if (havenext) {
                const float4* xt4 = reinterpret_cast<const float4*>(
                    xb + (size_t)(i + 1) * TILE_T * K_DIM);
#pragma unroll
                for (int q = 0; q < 4; ++q) xr[q] = __ldg(&xt4[pt + (q << 7)]);
            }

            // ---- GEMM tile i (3-term bf16 split), D init = bias
            float d[2][4][4];
#pragma unroll
            for (int mt = 0; mt < 2; ++mt)
#pragma unroll
                for (int nt = 0; nt < 4; ++nt) {
                    d[mt][nt][0] = bias0[mt]; d[mt][nt][1] = bias0[mt];
                    d[mt][nt][2] = bias1[mt]; d[mt][nt][3] = bias1[mt];
                }
            const uint32_t bX_hi = sb + XBUF(i & 1) + b_off;
            const uint32_t bX_lo = bX_hi + 4608;
#pragma unroll
            for (int ks = 0; ks < 4; ++ks) {
                uint32_t alo[2][4], bh[2][4], bl[2][4];
                ldm_x4(alo[0], aW_lo + ks * 32);
                ldm_x4(alo[1], aW_lo + 16 * ROWB + ks * 32);
                ldm_x4(bh[0], bX_hi + ks * 32);
                ldm_x4(bh[1], bX_hi + 16 * ROWB + ks * 32);
                ldm_x4(bl[0], bX_lo + ks * 32);
                ldm_x4(bl[1], bX_lo + 16 * ROWB + ks * 32);
#pragma unroll
                for (int mt = 0; mt < 2; ++mt)
#pragma unroll
                    for (int nt = 0; nt < 4; ++nt) {
                        const uint32_t* bhp = &bh[nt >> 1][(nt & 1) * 2];
                        const uint32_t* blp = &bl[nt >> 1][(nt & 1) * 2];
                        mma_bf16(d[mt][nt], Ahi[mt][ks], bhp);
                        mma_bf16(d[mt][nt], Ahi[mt][ks], blp);
                        mma_bf16(d[mt][nt], alo[mt], bhp);
                    }
            }

            // wait for slot s to be free (consumer freed it right after LDS)
            if (i >= 3) BAR_SYNC(4 + s);

            // ---- store ff tile, layout [t][h], stride 132 (conflict-free)
            {
                float* ffp = reinterpret_cast<float*>(smem + FFB(s));
                const int baser = pw * 32 + r0;
#pragma unroll
                for (int mt = 0; mt < 2; ++mt) {
                    const int row = baser + mt * 16;
#pragma unroll
                    for (int nt = 0; nt < 4; ++nt) {
                        const int col = nt * 8 + c0;
                        ffp[col * FF_STR + row]             = d[mt][nt][0];
                        ffp[(col + 1) * FF_STR + row]       = d[mt][nt][1];
                        ffp[col * FF_STR + row + 8]         = d[mt][nt][2];
                        ffp[(col + 1) * FF_STR + row + 8]   = d[mt][nt][3];
                    }
                }
            }
            BAR_ARRIVE(1 + s);

            // ---- convert prefetched tile i+1
            if (havenext) {
#pragma unroll
                for (int q = 0; q < 4; ++q) {
                    int idx = pt + (q << 7);
                    int row = idx >> 4, c4 = idx & 15;
                    uint32_t off = (uint32_t)row * ROWB + c4 * 8;
                    uint2 hi, lo; cvt_pack(xr[q], hi, lo);
                    *reinterpret_cast<uint2*>(smem + XBUF((i + 1) & 1) + off)        = hi;
                    *reinterpret_cast<uint2*>(smem + XBUF((i + 1) & 1) + 4608 + off) = lo;
                }
                asm volatile("bar.sync 7, 128;" ::: "memory");
            }
        }
    } else {
        // ==================== CONSUMERS ====================
        const int h = tid;                        // head index
        float mem = 0.0f, spk = 0.0f, wv = -2.5f; // wv = 2.25*mem - 2.5
        float* outp = out + (size_t)b * T_DIM * H_DIM + h;

        for (int i = 0; i < N_TILES; ++i) {
            const int s = i - (i / 3) * 3;        // i % 3
            BAR_SYNC(1 + s);

            const float* fp = reinterpret_cast<const float*>(smem + FFB(s)) + h;
            float r[TILE_T];
#pragma unroll
            for (int t = 0; t < TILE_T; ++t) r[t] = fp[t * FF_STR];

            BAR_ARRIVE(4 + s);                    // free slot immediately

            float* po = outp + (size_t)i * TILE_T * H_DIM;
#pragma unroll
            for (int t = 0; t < TILE_T; ++t) {
                float p  = r[t] - spk;            // ff (incl bias) - spk
                float y  = fmaf(p, 2.5f, wv);     // 2.5*(mem' - 1)
                float th = tanhf_approx(y);
                spk = fmaf(th, 0.5f, 0.5f);
                mem = fmaf(0.9f, mem, p);
                wv  = fmaf(mem, 2.25f, -2.5f);    // ready well before next use
                po[(size_t)t * H_DIM] = spk;
            }
        }
    }
}

// ============================================================================
// Launch. Inputs: x [256,2048,64] f32, W [128,64] f32, b [128] f32 -> out f32
// ============================================================================
extern "C" void kernel_launch(void* const* d_in, const int* in_sizes, int n_in,
                              void* d_out, int out_size) {
    const float* x = (const float*)d_in[0];
    const float* W = (const float*)d_in[1];
    const float* b = (const float*)d_in[2];
    float* out = (float*)d_out;

    cudaFuncSetAttribute(snn_encoder_kernel,
                         cudaFuncAttributeMaxDynamicSharedMemorySize, SMEM_TOTAL);
    snn_encoder_kernel<<<B_DIM, 256, SMEM_TOTAL>>>(x, W, b, out);
}

// round 5
// speedup vs baseline: 1.9851x; 1.3301x over previous
#include <cuda_runtime.h>
#include <cuda_bf16.h>
#include <cstdint>

// ============================================================================
// Problem constants
// ============================================================================
#define B_DIM   256
#define T_DIM   2048
#define K_DIM   64
#define H_DIM   128
#define TILE_T  32
#define N_TILES (T_DIM / TILE_T)   // 64

// Scan refactor: y_t = 2.5*(mem_t - 1), th = tanh(y), spk = 0.5*th + 0.5
//   y_t = 0.9*y_{t-1} - 1.25*th_{t-1} + g_t,  g_t = 2.5*ff_t - 1.5
// (2.5 folded into W, -1.5 + 2.5*b folded into bias => GEMM outputs g directly)

// ============================================================================
// SMEM layout (bytes)
//   [0, 27648)        x ring: 3 slots x 9216 (hi 4608 + lo 4608), 32x144B rows
//   [27648, 46080)    W_lo persistent (128 x 144 B)
//   [46080, 96768)    ff ring: 3 slots x 16896 ([t][h], stride 132 floats)
//   W_hi (init only) aliases ff region at 46080.
// ============================================================================
#define WSTR      72
#define ROWB      144
#define XBUF(s)   ((s) * 9216)
#define SMEM_W_LO 27648
#define SMEM_FF   46080
#define FFB(s)    (SMEM_FF + (s) * 16896)
#define FF_STR    132
#define SMEM_W_HI 46080
#define SMEM_TOTAL 96768

// Named barriers (256 threads unless noted):
//   FFREADY(s)=1+s, FFFREE(s)=4+s, XREADY(s)=7+s, XFREE(s)=10+s
//   13 = producer-only (128)
#define BAR_SYNC(id)   asm volatile("bar.sync %0, 256;"   :: "r"(id) : "memory")
#define BAR_ARRIVE(id) asm volatile("bar.arrive %0, 256;" :: "r"(id) : "memory")

// ============================================================================
// Helpers
// ============================================================================
__device__ __forceinline__ uint32_t smem_to_u32(const void* p) {
    uint32_t a;
    asm("{ .reg .u64 t; cvta.to.shared.u64 t, %1; cvt.u32.u64 %0, t; }"
        : "=r"(a) : "l"(p));
    return a;
}
__device__ __forceinline__ float tanhf_approx(float x) {
    float y; asm("tanh.approx.f32 %0, %1;" : "=f"(y) : "f"(x)); return y;
}
__device__ __forceinline__ void ldm_x4(uint32_t* r, uint32_t addr) {
    asm volatile("ldmatrix.sync.aligned.m8n8.x4.shared.b16 {%0,%1,%2,%3}, [%4];"
        : "=r"(r[0]), "=r"(r[1]), "=r"(r[2]), "=r"(r[3]) : "r"(addr));
}
__device__ __forceinline__ void mma_bf16(float* d, const uint32_t* a, const uint32_t* b) {
    asm volatile(
        "mma.sync.aligned.m16n8k16.row.col.f32.bf16.bf16.f32 "
        "{%0,%1,%2,%3},{%4,%5,%6,%7},{%8,%9},{%0,%1,%2,%3};"
        : "+f"(d[0]), "+f"(d[1]), "+f"(d[2]), "+f"(d[3])
        : "r"(a[0]), "r"(a[1]), "r"(a[2]), "r"(a[3]), "r"(b[0]), "r"(b[1]));
}
__device__ __forceinline__ uint32_t pack_bf16(__nv_bfloat16 a, __nv_bfloat16 b) {
    return ((uint32_t)__bfloat16_as_ushort(b) << 16) | __bfloat16_as_ushort(a);
}
__device__ __forceinline__ void cvt_pack(float4 v, uint2& hi, uint2& lo) {
    __nv_bfloat16 h0 = __float2bfloat16(v.x);
    __nv_bfloat16 h1 = __float2bfloat16(v.y);
    __nv_bfloat16 h2 = __float2bfloat16(v.z);
    __nv_bfloat16 h3 = __float2bfloat16(v.w);
    __nv_bfloat16 l0 = __float2bfloat16(v.x - __bfloat162float(h0));
    __nv_bfloat16 l1 = __float2bfloat16(v.y - __bfloat162float(h1));
    __nv_bfloat16 l2 = __float2bfloat16(v.z - __bfloat162float(h2));
    __nv_bfloat16 l3 = __float2bfloat16(v.w - __bfloat162float(h3));
    hi.x = pack_bf16(h0, h1); hi.y = pack_bf16(h2, h3);
    lo.x = pack_bf16(l0, l1); lo.y = pack_bf16(l2, l3);
}

// consumer-side: convert xr regs -> x ring slot s (swizzle-free padded layout)
__device__ __forceinline__ void convert_to_slot(char* smem, int s, int ct,
                                                const float4* xr) {
#pragma unroll
    for (int q = 0; q < 4; ++q) {
        int idx = ct + (q << 7);
        int row = idx >> 4, c4 = idx & 15;
        uint32_t off = (uint32_t)row * ROWB + c4 * 8;
        uint2 hi, lo; cvt_pack(xr[q], hi, lo);
        *reinterpret_cast<uint2*>(smem + XBUF(s) + off)        = hi;
        *reinterpret_cast<uint2*>(smem + XBUF(s) + 4608 + off) = lo;
    }
}

// ============================================================================
// Warp-specialized kernel. 1 CTA / batch, 256 threads.
//   tid 0..127  : consumers — tanh scan chain (thread = head) + x load/convert
//   tid 128..255: producers — lean HMMA GEMM (LDSM+MMA+STS only)
// ============================================================================
__global__ void __launch_bounds__(256, 2)
snn_encoder_kernel(const float* __restrict__ x, const float* __restrict__ W,
                   const float* __restrict__ bvec, float* __restrict__ out) {
    extern __shared__ char smem[];
    const uint32_t sb = smem_to_u32(smem);
    const int tid = threadIdx.x;
    const int b   = blockIdx.x;
    const float* xb = x + (size_t)b * T_DIM * K_DIM;

    // ---- Cooperative W convert: (2.5*W) fp32 -> bf16 hi/lo (hi aliases ff)
    {
        const float4* w4 = reinterpret_cast<const float4*>(W);
#pragma unroll
        for (int q = 0; q < 8; ++q) {
            int idx = tid + (q << 8);            // 2048 float4
            float4 v = __ldg(&w4[idx]);
            v.x *= 2.5f; v.y *= 2.5f; v.z *= 2.5f; v.w *= 2.5f;
            int row = idx >> 4, c4 = idx & 15;
            uint32_t off = (uint32_t)row * ROWB + c4 * 8;
            uint2 hi, lo; cvt_pack(v, hi, lo);
            *reinterpret_cast<uint2*>(smem + SMEM_W_HI + off) = hi;
            *reinterpret_cast<uint2*>(smem + SMEM_W_LO + off) = lo;
        }
    }
    __syncthreads();

    if (tid >= 128) {
        // ==================== PRODUCERS (lean GEMM) ====================
        const int pt   = tid - 128;
        const int lane = pt & 31;
        const int pw   = pt >> 5;                // heads [32pw, 32pw+32)
        const int j    = lane >> 3;

        const uint32_t a_off = (uint32_t)(((j & 1) * 8 + (lane & 7)) * WSTR + ((j >> 1) * 8)) * 2;
        const uint32_t b_off = (uint32_t)(((j >> 1) * 8 + (lane & 7)) * WSTR + ((j & 1) * 8)) * 2;
        const uint32_t aW_lo = sb + SMEM_W_LO + (uint32_t)(pw * 32) * ROWB + a_off;

        // hoist W_hi fragments (ff ring aliases this region afterwards)
        uint32_t Ahi[2][4][4];
        {
            const uint32_t aW_hi = sb + SMEM_W_HI + (uint32_t)(pw * 32) * ROWB + a_off;
#pragma unroll
            for (int mt = 0; mt < 2; ++mt)
#pragma unroll
                for (int ks = 0; ks < 4; ++ks)
                    ldm_x4(Ahi[mt][ks], aW_hi + (uint32_t)mt * 16 * ROWB + ks * 32);
        }
        // all producers done hoisting before any ff STS can overwrite W_hi
        asm volatile("bar.sync 13, 128;" ::: "memory");

        // bias' = 2.5*b - 1.5 folded into accumulator init
        const int r0 = lane >> 2;
        const int c0 = 2 * (lane & 3);
        float bias0[2], bias1[2];
#pragma unroll
        for (int mt = 0; mt < 2; ++mt) {
            bias0[mt] = fmaf(__ldg(&bvec[pw * 32 + mt * 16 + r0]), 2.5f, -1.5f);
            bias1[mt] = fmaf(__ldg(&bvec[pw * 32 + mt * 16 + r0 + 8]), 2.5f, -1.5f);
        }

        int sx = 0, sf = 0;
        for (int i = 0; i < N_TILES; ++i) {
            BAR_SYNC(7 + sx);                    // wait x tile i converted

            float d[2][4][4];
#pragma unroll
            for (int mt = 0; mt < 2; ++mt)
#pragma unroll
                for (int nt = 0; nt < 4; ++nt) {
                    d[mt][nt][0] = bias0[mt]; d[mt][nt][1] = bias0[mt];
                    d[mt][nt][2] = bias1[mt]; d[mt][nt][3] = bias1[mt];
                }
            const uint32_t bX_hi = sb + XBUF(sx) + b_off;
            const uint32_t bX_lo = bX_hi + 4608;
#pragma unroll
            for (int ks = 0; ks < 4; ++ks) {
                uint32_t alo[2][4], bh[2][4], bl[2][4];
                ldm_x4(alo[0], aW_lo + ks * 32);
                ldm_x4(alo[1], aW_lo + 16 * ROWB + ks * 32);
                ldm_x4(bh[0], bX_hi + ks * 32);
                ldm_x4(bh[1], bX_hi + 16 * ROWB + ks * 32);
                ldm_x4(bl[0], bX_lo + ks * 32);
                ldm_x4(bl[1], bX_lo + 16 * ROWB + ks * 32);
#pragma unroll
                for (int mt = 0; mt < 2; ++mt)
#pragma unroll
                    for (int nt = 0; nt < 4; ++nt) {
                        const uint32_t* bhp = &bh[nt >> 1][(nt & 1) * 2];
                        const uint32_t* blp = &bl[nt >> 1][(nt & 1) * 2];
                        mma_bf16(d[mt][nt], Ahi[mt][ks], bhp);
                        mma_bf16(d[mt][nt], Ahi[mt][ks], blp);
                        mma_bf16(d[mt][nt], alo[mt], bhp);
                    }
            }
            BAR_ARRIVE(10 + sx);                 // x slot free (LDSM done)

            if (i >= 3) BAR_SYNC(4 + sf);        // wait ff slot free

            // store ff tile, layout [t][h], stride 132 (conflict-free)
            {
                float* ffp = reinterpret_cast<float*>(smem + FFB(sf));
                const int baser = pw * 32 + r0;
#pragma unroll
                for (int mt = 0; mt < 2; ++mt) {
                    const int row = baser + mt * 16;
#pragma unroll
                    for (int nt = 0; nt < 4; ++nt) {
                        const int col = nt * 8 + c0;
                        ffp[col * FF_STR + row]           = d[mt][nt][0];
                        ffp[(col + 1) * FF_STR + row]     = d[mt][nt][1];
                        ffp[col * FF_STR + row + 8]       = d[mt][nt][2];
                        ffp[(col + 1) * FF_STR + row + 8] = d[mt][nt][3];
                    }
                }
            }
            BAR_ARRIVE(1 + sf);                  // ff tile ready

            if (++sx == 3) sx = 0;
            if (++sf == 3) sf = 0;
        }
    } else {
        // ==================== CONSUMERS (scan + x feed) ====================
        const int h  = tid;
        const int ct = tid;                      // convert-thread index
        float* outp = out + (size_t)b * T_DIM * H_DIM + h;

        // prologue: convert x tiles 0,1 into slots 0,1; prefetch tile 2
        float4 xr[4];
        {
            const float4* x4 = reinterpret_cast<const float4*>(xb);
#pragma unroll
            for (int q = 0; q < 4; ++q) xr[q] = __ldg(&x4[ct + (q << 7)]);
            convert_to_slot(smem, 0, ct, xr);
            BAR_ARRIVE(7 + 0);
            x4 = reinterpret_cast<const float4*>(xb + (size_t)TILE_T * K_DIM);
#pragma unroll
            for (int q = 0; q < 4; ++q) xr[q] = __ldg(&x4[ct + (q << 7)]);
            convert_to_slot(smem, 1, ct, xr);
            BAR_ARRIVE(7 + 1);
            x4 = reinterpret_cast<const float4*>(xb + (size_t)2 * TILE_T * K_DIM);
#pragma unroll
            for (int q = 0; q < 4; ++q) xr[q] = __ldg(&x4[ct + (q << 7)]);
        }

        // scan state: z = 0.9*y_{-1} - 1.25*th_{-1} = -1.0 (mem=0, spk=0)
        float z = -1.0f;
        int sf = 0, sx = 2;                      // next convert slot = tile 2

        for (int i = 0; i < N_TILES; ++i) {
            // convert tile i+2 (regs loaded last iter), then prefetch i+3
            if (i + 2 < N_TILES) {
                if (i + 2 >= 3) BAR_SYNC(10 + sx);
                convert_to_slot(smem, sx, ct, xr);
                BAR_ARRIVE(7 + sx);
                if (++sx == 3) sx = 0;
            }
            if (i + 3 < N_TILES) {
                const float4* x4 = reinterpret_cast<const float4*>(
                    xb + (size_t)(i + 3) * TILE_T * K_DIM);
#pragma unroll
                for (int q = 0; q < 4; ++q) xr[q] = __ldg(&x4[ct + (q << 7)]);
            }

            BAR_SYNC(1 + sf);                    // wait ff tile i
            const float* fp = reinterpret_cast<const float*>(smem + FFB(sf)) + h;
            float g[TILE_T];
#pragma unroll
            for (int t = 0; t < TILE_T; ++t) g[t] = fp[t * FF_STR];
            BAR_ARRIVE(4 + sf);                  // free ff slot immediately
            if (++sf == 3) sf = 0;

            float* po = outp + (size_t)i * TILE_T * H_DIM;
            float y = z + g[0];
#pragma unroll
            for (int t = 0; t < TILE_T; ++t) {
                float th = tanhf_approx(y);          // MUFU (critical path)
                float gn = (t < TILE_T - 1) ? g[t + 1] : 0.0f;
                float a  = fmaf(0.9f, y, gn);        // parallel with tanh
                y = fmaf(th, -1.25f, a);             // y_{t+1} (or z at t=31)
                float spk = fmaf(th, 0.5f, 0.5f);    // off critical path
                po[(size_t)t * H_DIM] = spk;
            }
            z = y;                               // carry partial to next tile
        }
    }
}

// ============================================================================
// Launch. Inputs: x [256,2048,64] f32, W [128,64] f32, b [128] f32 -> out f32
// ============================================================================
extern "C" void kernel_launch(void* const* d_in, const int* in_sizes, int n_in,
                              void* d_out, int out_size) {
    const float* x = (const float*)d_in[0];
    const float* W = (const float*)d_in[1];
    const float* b = (const float*)d_in[2];
    float* out = (float*)d_out;

    cudaFuncSetAttribute(snn_encoder_kernel,
                         cudaFuncAttributeMaxDynamicSharedMemorySize, SMEM_TOTAL);
    snn_encoder_kernel<<<B_DIM, 256, SMEM_TOTAL>>>(x, W, b, out);
}